// round 6
// baseline (speedup 1.0000x reference)
#include <cuda_runtime.h>
#include <math.h>

#define B_  64
#define T_  2048
#define IN_ 128
#define H_  256
#define M_  (B_ * T_)

// ---------------- scratch (static device allocations; no cudaMalloc) ----------------
__device__ float g_xp[(size_t)B_ * T_ * H_];    // reused for xp0 then xp1
__device__ float g_h1[(size_t)B_ * T_ * H_];    // layer-0 hidden states
__device__ float g_h2last[(size_t)B_ * H_];     // h2[:, T-1, :]

// ---------------- packed fp32x2 helpers (sm_103a) ----------------
__device__ __forceinline__ void fma2(unsigned long long &d, unsigned long long a, unsigned long long b) {
    asm("fma.rn.f32x2 %0, %1, %2, %0;" : "+l"(d) : "l"(a), "l"(b));
}
__device__ __forceinline__ unsigned long long splat2(float x) {
    unsigned long long r; asm("mov.b64 %0, {%1, %1};" : "=l"(r) : "f"(x)); return r;
}
__device__ __forceinline__ float lo2(unsigned long long v) { return __uint_as_float((unsigned)(v & 0xffffffffULL)); }
__device__ __forceinline__ float hi2(unsigned long long v) { return __uint_as_float((unsigned)(v >> 32)); }

// fast tanh: 1 - 2/(exp(2x)+1) via MUFU ex2/rcp; abs err ~5e-7, monotone, saturates
__device__ __forceinline__ float tanh_fast(float s) {
    s = fminf(fmaxf(s, -15.f), 15.f);
    float e;
    asm("ex2.approx.f32 %0, %1;" : "=f"(e) : "f"(s * 2.885390082f));
    float r;
    asm("rcp.approx.f32 %0, %1;" : "=f"(r) : "f"(e + 1.f));
    return fmaf(-2.f, r, 1.f);
}

// ---------------- cluster / mbarrier helpers ----------------
__device__ __forceinline__ unsigned su32(const void* p) {
    return (unsigned)__cvta_generic_to_shared(p);
}
__device__ __forceinline__ unsigned cta_rank() {
    unsigned r; asm("mov.u32 %0, %%cluster_ctarank;" : "=r"(r)); return r;
}
__device__ __forceinline__ unsigned mapa_u32(unsigned addr, unsigned rank) {
    unsigned r; asm("mapa.shared::cluster.u32 %0, %1, %2;" : "=r"(r) : "r"(addr), "r"(rank));
    return r;
}
__device__ __forceinline__ void mbar_init(unsigned addr, unsigned cnt) {
    asm volatile("mbarrier.init.shared.b64 [%0], %1;" :: "r"(addr), "r"(cnt) : "memory");
}
__device__ __forceinline__ void mbar_expect_tx(unsigned addr, unsigned bytes) {
    asm volatile("mbarrier.arrive.expect_tx.shared.b64 _, [%0], %1;" :: "r"(addr), "r"(bytes) : "memory");
}
__device__ __forceinline__ void mbar_wait_cluster(unsigned addr, unsigned parity) {
    asm volatile(
        "{\n\t.reg .pred P;\n\t"
        "WL_%=:\n\t"
        "mbarrier.try_wait.parity.acquire.cluster.shared::cta.b64 P, [%0], %1, 0x989680;\n\t"
        "@P bra.uni WD_%=;\n\t"
        "bra.uni WL_%=;\n\t"
        "WD_%=:\n\t}"
        :: "r"(addr), "r"(parity) : "memory");
}
__device__ __forceinline__ void st_async_f32(unsigned remote_addr, float v, unsigned remote_mbar) {
    asm volatile(
        "st.async.shared::cluster.mbarrier::complete_tx::bytes.b32 [%0], %1, [%2];"
        :: "r"(remote_addr), "r"(__float_as_uint(v)), "r"(remote_mbar) : "memory");
}
__device__ __forceinline__ void cluster_sync_() {
    asm volatile("barrier.cluster.arrive.aligned;" ::: "memory");
    asm volatile("barrier.cluster.wait.aligned;" ::: "memory");
}

// =====================================================================================
// Phase A / C: C[m][n] = sum_k A[m][k] * W[n][k] + bias0[n] + bias1[n]
// =====================================================================================
__global__ __launch_bounds__(256, 2)
void gemm_bias_kernel(const float* __restrict__ A, const float* __restrict__ W,
                      const float* __restrict__ bias0, const float* __restrict__ bias1,
                      float* __restrict__ C, int K)
{
    __shared__ float a_sm[16][132];
    __shared__ float b_sm[16][132];

    const int tid = threadIdx.x;
    const int tx = tid & 15, ty = tid >> 4;
    const int mBase = blockIdx.x * 128;
    const int nBase = blockIdx.y * 128;

    unsigned long long acc[8][4];
#pragma unroll
    for (int i = 0; i < 8; i++)
#pragma unroll
        for (int j = 0; j < 4; j++) acc[i][j] = 0ULL;

    for (int kt = 0; kt < K; kt += 16) {
#pragma unroll
        for (int l = 0; l < 2; l++) {
            int idx = l * 256 + tid;
            int row = idx >> 2, kq = idx & 3;
            float4 v = *(const float4*)(A + (size_t)(mBase + row) * K + kt + kq * 4);
            a_sm[kq * 4 + 0][row] = v.x; a_sm[kq * 4 + 1][row] = v.y;
            a_sm[kq * 4 + 2][row] = v.z; a_sm[kq * 4 + 3][row] = v.w;
        }
#pragma unroll
        for (int l = 0; l < 2; l++) {
            int idx = l * 256 + tid;
            int row = idx >> 2, kq = idx & 3;
            float4 v = *(const float4*)(W + (size_t)(nBase + row) * K + kt + kq * 4);
            b_sm[kq * 4 + 0][row] = v.x; b_sm[kq * 4 + 1][row] = v.y;
            b_sm[kq * 4 + 2][row] = v.z; b_sm[kq * 4 + 3][row] = v.w;
        }
        __syncthreads();

#pragma unroll
        for (int kk = 0; kk < 16; kk++) {
            float4 a0 = *(const float4*)&a_sm[kk][ty * 8];
            float4 a1 = *(const float4*)&a_sm[kk][ty * 8 + 4];
            ulonglong2 b0 = *(const ulonglong2*)&b_sm[kk][tx * 8];
            ulonglong2 b1 = *(const ulonglong2*)&b_sm[kk][tx * 8 + 4];
            float av[8] = {a0.x, a0.y, a0.z, a0.w, a1.x, a1.y, a1.z, a1.w};
#pragma unroll
            for (int i = 0; i < 8; i++) {
                unsigned long long s = splat2(av[i]);
                fma2(acc[i][0], s, b0.x);
                fma2(acc[i][1], s, b0.y);
                fma2(acc[i][2], s, b1.x);
                fma2(acc[i][3], s, b1.y);
            }
        }
        __syncthreads();
    }

    const int n0 = nBase + tx * 8;
    float bj[8];
#pragma unroll
    for (int j = 0; j < 8; j++) bj[j] = bias0[n0 + j] + bias1[n0 + j];

#pragma unroll
    for (int i = 0; i < 8; i++) {
        int m = mBase + ty * 8 + i;
        float4 o0, o1;
        o0.x = lo2(acc[i][0]) + bj[0]; o0.y = hi2(acc[i][0]) + bj[1];
        o0.z = lo2(acc[i][1]) + bj[2]; o0.w = hi2(acc[i][1]) + bj[3];
        o1.x = lo2(acc[i][2]) + bj[4]; o1.y = hi2(acc[i][2]) + bj[5];
        o1.z = lo2(acc[i][3]) + bj[6]; o1.w = hi2(acc[i][3]) + bj[7];
        *(float4*)(C + (size_t)m * H_ + n0)     = o0;
        *(float4*)(C + (size_t)m * H_ + n0 + 4) = o1;
    }
}

// =====================================================================================
// Recurrence v4 (partial-sum exchange): 64 clusters x 2 CTAs, 1 batch row/cluster.
// CTA rank r keeps ONLY its h-chunk h_r = h[128r .. 128r+128) locally, and per step
// computes partials over its OWN k-half for ALL 256 outputs:
//     y[o] = W[o, 128r:128r+128) @ h_r[t-1]        (needs no peer data!)
// Warps 0-3 (tid<128) compute the 128 PEER-destined outputs first and st.async the
// partials immediately (~150 cyc into the step) -> flight overlaps the rest.
// Warps 4-7 compute OWN-output partials, wait the mbar for the peer's partials,
// combine + xp + tanh, store h_r[t]. Only warps 4-7 ever block on the mbar.
// Double buffer h_sm and p_rcv; mbar[t&1], parity (t>>1)&1, expect_tx 512B.
// =====================================================================================
template<bool STORE_ALL>
__global__ void __cluster_dims__(2, 1, 1) __launch_bounds__(256, 1)
rnn_rec4(const float* __restrict__ xp, const float* __restrict__ Whh,
         float* __restrict__ hout)
{
    __shared__ __align__(16) float h_sm[2][132];    // own h chunk (double buffered)
    __shared__ __align__(16) float p_rcv[2][128];   // incoming peer partials
    __shared__ __align__(8)  unsigned long long mbar[2];

    const int tid = threadIdx.x;
    const unsigned rank = cta_rank();              // 0 or 1
    const unsigned peer = rank ^ 1u;
    const int b = blockIdx.x >> 1;                 // batch row
    const int is_recv = tid >> 7;                  // 0: sender warps, 1: receiver warps
    const int oi = tid & 127;
    const int o_glob = (is_recv ? (int)rank : (int)peer) * 128 + oi;

    // ---- W slice: Whh[o_glob][rank*128 .. +128) as 32 ulonglong2 (128 floats) ----
    unsigned long long wq[64];
    {
        const ulonglong2* src = (const ulonglong2*)(Whh + (size_t)o_glob * H_ + (int)rank * 128);
#pragma unroll
        for (int j = 0; j < 32; ++j) { ulonglong2 v = src[j]; wq[2 * j] = v.x; wq[2 * j + 1] = v.y; }
    }

    // ---- init ----
    if (tid == 0) { mbar_init(su32(&mbar[0]), 1); mbar_init(su32(&mbar[1]), 1); }
    for (int i = tid; i < 2 * 132; i += 256) ((float*)h_sm)[i] = 0.f;   // h[-1] = 0
    __syncthreads();
    cluster_sync_();                                // peer mbars live

    const unsigned my_mbar   = su32(&mbar[0]);
    const unsigned peer_mbar = mapa_u32(my_mbar, peer);
    const unsigned peer_prcv = mapa_u32(su32(&p_rcv[0][0]), peer);

    const size_t xrow = ((size_t)b * T_) * H_ + o_glob;
    float xv = is_recv ? __ldg(xp + xrow) : 0.f;    // xp[b][0][o_glob]

    for (int t = 0; t < T_; ++t) {
        const int cb = t & 1, nb = cb ^ 1;

        // prefetch xp for t+1 (LDG latency hidden under matvec + wait)
        float xvn = 0.f;
        if (is_recv && t + 1 < T_) xvn = __ldg(xp + xrow + (size_t)(t + 1) * H_);

        if (tid == 0) mbar_expect_tx(my_mbar + (unsigned)cb * 8u, 512u);

        // ---- matvec over OWN h chunk (local, no peer dependency) ----
        const float* hb = &h_sm[cb][0];
        unsigned long long a0 = 0, a1 = 0, a2 = 0, a3 = 0;
#pragma unroll
        for (int kk = 0; kk < 32; kk += 2) {
            ulonglong2 v0 = *(const ulonglong2*)(hb + kk * 4);       // broadcast LDS.128
            ulonglong2 v1 = *(const ulonglong2*)(hb + kk * 4 + 4);
            fma2(a0, v0.x, wq[2 * kk]);
            fma2(a1, v0.y, wq[2 * kk + 1]);
            fma2(a2, v1.x, wq[2 * kk + 2]);
            fma2(a3, v1.y, wq[2 * kk + 3]);
        }
        float p = lo2(a0) + hi2(a0) + lo2(a1) + hi2(a1)
                + lo2(a2) + hi2(a2) + lo2(a3) + hi2(a3);

        if (!is_recv) {
            // sender: ship partial for peer output o_glob NOW (early in the step)
            st_async_f32(peer_prcv + (unsigned)(cb * 128 + oi) * 4u,
                         p, peer_mbar + (unsigned)cb * 8u);
        } else {
            // receiver: wait for peer partials of THIS step, combine, activate
            mbar_wait_cluster(my_mbar + (unsigned)cb * 8u, (unsigned)(t >> 1) & 1u);
            float h = tanh_fast(xv + p + p_rcv[cb][oi]);
            h_sm[nb][oi] = h;                                         // h_r[t] for t+1
            if (STORE_ALL)
                hout[((size_t)b * T_ + t) * H_ + o_glob] = h;
            else if (t == T_ - 1)
                hout[(size_t)b * H_ + o_glob] = h;
        }
        __syncthreads();
        xv = xvn;
    }
    cluster_sync_();   // receivers consumed all incoming phases; keep both CTAs alive
}

// =====================================================================================
// Final FC: out[b] = dot(h2last[b, :], W_fc[0,:]) + b_fc[0]
// =====================================================================================
__global__ void fc_kernel(const float* __restrict__ h2l, const float* __restrict__ Wfc,
                          const float* __restrict__ bfc, float* __restrict__ out)
{
    __shared__ float red[8];
    int b = blockIdx.x, tid = threadIdx.x;
    float v = h2l[(size_t)b * H_ + tid] * Wfc[tid];
#pragma unroll
    for (int o = 16; o > 0; o >>= 1) v += __shfl_down_sync(0xffffffffu, v, o);
    if ((tid & 31) == 0) red[tid >> 5] = v;
    __syncthreads();
    if (tid < 8) {
        float s = red[tid];
#pragma unroll
        for (int o = 4; o > 0; o >>= 1) s += __shfl_down_sync(0xffu, s, o);
        if (tid == 0) out[b] = s + bfc[0];
    }
}

// =====================================================================================
extern "C" void kernel_launch(void* const* d_in, const int* in_sizes, int n_in,
                              void* d_out, int out_size)
{
    const float* x     = (const float*)d_in[0];
    const float* W_ih0 = (const float*)d_in[1];
    const float* W_hh0 = (const float*)d_in[2];
    const float* b_ih0 = (const float*)d_in[3];
    const float* b_hh0 = (const float*)d_in[4];
    const float* W_ih1 = (const float*)d_in[5];
    const float* W_hh1 = (const float*)d_in[6];
    const float* b_ih1 = (const float*)d_in[7];
    const float* b_hh1 = (const float*)d_in[8];
    const float* W_fc  = (const float*)d_in[9];
    const float* b_fc  = (const float*)d_in[10];
    float* out = (float*)d_out;

    float *xp, *h1, *h2l;
    cudaGetSymbolAddress((void**)&xp, g_xp);
    cudaGetSymbolAddress((void**)&h1, g_h1);
    cudaGetSymbolAddress((void**)&h2l, g_h2last);

    dim3 ggemm(M_ / 128, H_ / 128);

    // Phase A: xp0 = x @ W_ih0^T + b_ih0 + b_hh0
    gemm_bias_kernel<<<ggemm, 256>>>(x, W_ih0, b_ih0, b_hh0, xp, IN_);
    // Phase B: layer-0 recurrence -> h1 (streams all steps)
    rnn_rec4<true><<<128, 256>>>(xp, W_hh0, h1);
    // Phase C: xp1 = h1 @ W_ih1^T + b_ih1 + b_hh1
    gemm_bias_kernel<<<ggemm, 256>>>(h1, W_ih1, b_ih1, b_hh1, xp, H_);
    // Phase D: layer-1 recurrence -> only h2[T-1]
    rnn_rec4<false><<<128, 256>>>(xp, W_hh1, h2l);
    // Phase E: final projection
    fc_kernel<<<B_, H_>>>(h2l, W_fc, b_fc, out);
}